// round 13
// baseline (speedup 1.0000x reference)
#include <cuda_runtime.h>
#include <cuda_fp16.h>
#include <cstdint>

// Problem constants
#define D_IN   256
#define D_OUT  256
#define BATCH  512
#define KNOTS  64
#define INV_H  15.75f          // 63/4, exact in fp32
#define H_VAL  (4.0f/63.0f)

#define NCHUNK 32              // din chunks
#define DCHUNK 8               // din per chunk
#define TB     256             // batch rows per block

// B tile: 64 knots x 32 pairs of uint4 {y2(p), hm2(p), y2(p+32), hm2(p+32)} = 32KB
#define TILE_U4   (64*32)      // 2048 uint4
#define TILE_BYTES (TILE_U4*16)

// B smem bytes: 2 tiles (64KB) + cw (32KB) + mbarriers
#define OFF_CW    (2*TILE_BYTES)
#define OFF_MBAR  (OFF_CW + 2048*16)
#define SMEM_BYTES (OFF_MBAR + 64)

// Scratch (device globals; no allocation)
__device__ uint4 g_pack2[(size_t)D_IN * 4 * TILE_U4];           // 33.5 MB

// ---------------------------------------------------------------------------
// PCHIP helpers in RAW-DELTA units.
// eps guard removed: p>0 implies den!=0 (same-sign nonzero); subnormal p
// underflows to 0 -> selects 0 branch naturally.
// ---------------------------------------------------------------------------
__device__ __forceinline__ float pchip_interior_raw(float D0, float D1) {
    float p   = D0 * D1;
    float m   = __fdividef(2.0f * p, D0 + D1);  // = H * harmonic-mean slope
    return (p > 0.0f) ? m : 0.0f;
}
__device__ __forceinline__ float pchip_endpoint_raw(float Dn, float Df) {
    float m = 1.5f * Dn - 0.5f * Df;            // = H * endpoint slope
    m = (m * Dn <= 0.0f) ? 0.0f : m;
    bool clamp3 = (Dn * Df < 0.0f) && (fabsf(m) > 3.0f * fabsf(Dn));
    return clamp3 ? 3.0f * Dn : m;
}

// 4 records (knots jb..jb+3) for one spline; two aligned LDS.128 window loads.
// Pad slots (0 and 65..67) hold garbage reaching only record 63 / overwritten
// endpoint slopes — never consumed downstream (idx <= 62).
__device__ __forceinline__ void spline4v(const float* __restrict__ rowbase, int jb,
                                         unsigned y2[4], unsigned h2[4]) {
    float4 a = *(const float4*)(rowbase + jb);       // ly[0..3]
    float4 b = *(const float4*)(rowbase + jb + 4);   // ly[4..7]
    float ly[7] = {a.x, a.y, a.z, a.w, b.x, b.y, b.z};

    float D[6];
#pragma unroll
    for (int k = 0; k < 6; ++k) D[k] = ly[k + 1] - ly[k];

    float s[5];
#pragma unroll
    for (int k = 0; k < 5; ++k) s[k] = pchip_interior_raw(D[k], D[k + 1]);
    if (jb == 0)  s[0] = pchip_endpoint_raw(D[1], D[2]);    // hm0
    if (jb == 60) s[3] = pchip_endpoint_raw(D[3], D[2]);    // hm63

#pragma unroll
    for (int kk = 0; kk < 4; ++kk) {
        __half2 yv = __floats2half2_rn(ly[kk + 1], ly[kk + 2]);
        __half2 hv = __floats2half2_rn(s[kk], s[kk + 1]);
        y2[kk] = *reinterpret_cast<unsigned*>(&yv);
        h2[kk] = *reinterpret_cast<unsigned*>(&hv);
    }
}

// ---------------------------------------------------------------------------
// Kernel A: PCHIP + pack. 4096 blocks x 128 threads (~16 resident/SM).
// Block (bx, qt): spline pairs p = qt*8+i (i<8) of dout-group bx.
// Thread (i = t&7, q = t>>3): records jb=4q..4q+3 for splines p and p+32.
// ---------------------------------------------------------------------------
__global__ void __launch_bounds__(128) pchip_pack_kernel(const float* __restrict__ y) {
    __shared__ float sy[16 * 68 + 4];              // pitch 68, data at slot +1

    const int t  = threadIdx.x;
    const int bx = blockIdx.x >> 2;                // din*4 + dxt
    const int qt = blockIdx.x & 3;                 // pair quarter

    const float* src = y + (size_t)bx * 4096;
#pragma unroll
    for (int f = t; f < 256; f += 128) {           // stage 4KB (16 rows x 64 knots)
        int r    = f >> 4;
        int col  = (f & 15) << 2;
        int spl  = qt * 8 + ((r < 8) ? r : (r + 24));   // r<8: p ; r>=8: p+32
        float4 v = *(const float4*)(src + spl * KNOTS + col);
        float* dp = sy + r * 68 + 1 + col;
        dp[0] = v.x; dp[1] = v.y; dp[2] = v.z; dp[3] = v.w;
    }
    __syncthreads();

    const int i  = t & 7;
    const int q  = t >> 3;                         // chunk 0..15
    const int jb = q << 2;                         // 0..60

    unsigned ya[4], hA[4], yb[4], hB[4];
    spline4v(sy + i * 68,       jb, ya, hA);       // spline qt*8+i
    spline4v(sy + (i + 8) * 68, jb, yb, hB);       // spline qt*8+i+32

    uint4* dst = g_pack2 + (size_t)bx * TILE_U4 + jb * 32 + (qt * 8 + i);
#pragma unroll
    for (int kk = 0; kk < 4; ++kk) {
        uint4 rec;
        rec.x = ya[kk]; rec.y = hA[kk]; rec.z = yb[kk]; rec.w = hB[kk];
        dst[kk * 32] = rec;
    }
}

// ---------------------------------------------------------------------------
// Kernel I: out = bias
// ---------------------------------------------------------------------------
__global__ void __launch_bounds__(256) init_out_kernel(
        const float* __restrict__ bias, float* __restrict__ out) {
    int i = blockIdx.x * 256 + threadIdx.x;
    ((float4*)out)[i] = ((const float4*)bias)[i & 63];
}

// ---------------------------------------------------------------------------
// mbarrier / bulk-copy helpers
// ---------------------------------------------------------------------------
__device__ __forceinline__ __half2 u2h(unsigned u) {
    return *reinterpret_cast<__half2*>(&u);
}
__device__ __forceinline__ void mbar_init(unsigned mbar, unsigned count) {
    asm volatile("mbarrier.init.shared.b64 [%0], %1;" :: "r"(mbar), "r"(count) : "memory");
}
__device__ __forceinline__ void mbar_expect_tx(unsigned mbar, unsigned tx) {
    asm volatile("mbarrier.arrive.expect_tx.shared.b64 _, [%0], %1;"
                 :: "r"(mbar), "r"(tx) : "memory");
}
__device__ __forceinline__ void bulk_copy(unsigned dst, const void* src, unsigned bytes,
                                          unsigned mbar) {
    asm volatile("cp.async.bulk.shared::cta.global.mbarrier::complete_tx::bytes "
                 "[%0], [%1], %2, [%3];"
                 :: "r"(dst), "l"(src), "r"(bytes), "r"(mbar) : "memory");
}
__device__ __forceinline__ void mbar_wait(unsigned mbar, unsigned parity) {
    unsigned done;
    asm volatile("{\n\t.reg .pred p;\n\t"
                 "mbarrier.try_wait.parity.acquire.cta.shared::cta.b64 p, [%1], %2;\n\t"
                 "selp.b32 %0, 1, 0, p;\n\t}"
                 : "=r"(done) : "r"(mbar), "r"(parity) : "memory");
    if (!done) {
        asm volatile("{\n\t.reg .pred P1;\n\t"
                     "WAIT_LOOP_%=:\n\t"
                     "mbarrier.try_wait.parity.acquire.cta.shared::cta.b64 P1, [%0], %1, 0x989680;\n\t"
                     "@P1 bra.uni WAIT_DONE_%=;\n\t"
                     "bra.uni WAIT_LOOP_%=;\n\t"
                     "WAIT_DONE_%=:\n\t}"
                     :: "r"(mbar), "r"(parity) : "memory");
    }
}

// ---------------------------------------------------------------------------
// Kernel B: main gather-accumulate.
// Grid (4 dxt, 2 by, 32 ch) = 256 blocks, 256 threads, 2 blocks/SM.
// Inner iter: broadcast LDS.128 + gather LDS.128 + 4 HFMA2 (fused half2
// accumulators); flushed to gmem via atomicAdd every 2 din (short fp16 chains).
// ---------------------------------------------------------------------------
__global__ void __launch_bounds__(256, 2) kan_main_kernel(
        const float* __restrict__ x, float* __restrict__ out) {
    extern __shared__ char smem[];
    uint4*   tile  = (uint4*)smem;                    // 2 x TILE_U4
    uint4*   cw    = (uint4*)(smem + OFF_CW);         // 2048: {wy, wh, byteoff, 0}
    unsigned smem_base;
    asm("{ .reg .u64 t; cvta.to.shared.u64 t, %1; cvt.u32.u64 %0, t; }"
        : "=r"(smem_base) : "l"(smem));
    const unsigned mbar0 = smem_base + OFF_MBAR;
    const unsigned mbar1 = smem_base + OFF_MBAR + 8;

    const int dx  = blockIdx.x;   // dout tile of 64 (0..3)
    const int by  = blockIdx.y;   // b tile (0..1)
    const int ch  = blockIdx.z;   // din chunk (0..31)
    const int tid = threadIdx.x;

    if (tid == 0) {
        mbar_init(mbar0, 1);
        mbar_init(mbar1, 1);
    }

    // ---- hermite weights + gather byte offset ----
    for (int i = tid; i < TB * DCHUNK; i += 256) {
        int bb = i >> 3, dl = i & 7;
        float xv = x[(by * TB + bb) * D_IN + ch * DCHUNK + dl];
        xv = fminf(fmaxf(xv, -2.0f), 2.0f);
        float tt = (xv + 2.0f) * INV_H;
        int idx = (int)floorf(tt);
        if (idx > KNOTS - 2) idx = KNOTS - 2;
        if (idx < 0) idx = 0;
        float u  = tt - (float)idx;
        float u2 = u * u, u3 = u2 * u;
        float h00 = 2.0f * u3 - 3.0f * u2 + 1.0f;
        float h10 = u3 - 2.0f * u2 + u;
        float h01 = 3.0f * u2 - 2.0f * u3;
        float h11 = u3 - u2;
        __half2 wy = __floats2half2_rn(h00, h01);
        __half2 wh = __floats2half2_rn(h10, h11);
        uint4 r;
        r.x = *reinterpret_cast<unsigned*>(&wy);
        r.y = *reinterpret_cast<unsigned*>(&wh);
        r.z = (unsigned)(idx << 9);          // idx * 512B (row = 32 uint4)
        r.w = 0;
        cw[i] = r;
    }
    __syncthreads();

    const int w = tid >> 5, l = tid & 31;
    __half2 ah0[32], ah1[32];
    const __half2 hzero = u2h(0u);
#pragma unroll
    for (int bb = 0; bb < 32; ++bb) { ah0[bb] = hzero; ah1[bb] = hzero; }

    float* O = out + ((size_t)by * TB + w * 32) * D_OUT + dx * 64;

    const uint4* gsrc = g_pack2 + ((size_t)ch * DCHUNK * 4 + dx) * TILE_U4;

    auto issue_copy = [&](int d, int st) {
        if (tid == 0) {
            unsigned mb = st ? mbar1 : mbar0;
            mbar_expect_tx(mb, TILE_BYTES);
            bulk_copy(smem_base + st * TILE_BYTES, gsrc + (size_t)d * 4 * TILE_U4,
                      TILE_BYTES, mb);
        }
    };

    issue_copy(0, 0);

    int phase0 = 0, phase1 = 0;

    for (int d = 0; d < DCHUNK; ++d) {
        const int st = d & 1;
        if (d < DCHUNK - 1) issue_copy(d + 1, st ^ 1);

        if (st == 0) { mbar_wait(mbar0, phase0); phase0 ^= 1; }
        else         { mbar_wait(mbar1, phase1); phase1 ^= 1; }

        const char* tb = (const char*)(tile + st * TILE_U4) + (l << 4);
        const int base = (w * 32) * DCHUNK + d;

        // software pipeline: records 2 ahead, gathers 1 ahead
        uint4 rA = cw[base];
        uint4 rB = cw[base + DCHUNK];
        uint4 gA = *(const uint4*)(tb + rA.z);
#pragma unroll
        for (int bb = 0; bb < 32; ++bb) {
            uint4 rC, gB;
            if (bb < 30) rC = cw[base + (bb + 2) * DCHUNK];
            if (bb < 31) gB = *(const uint4*)(tb + rB.z);

            ah0[bb] = __hfma2(u2h(rA.y), u2h(gA.y),
                       __hfma2(u2h(rA.x), u2h(gA.x), ah0[bb]));
            ah1[bb] = __hfma2(u2h(rA.y), u2h(gA.w),
                       __hfma2(u2h(rA.x), u2h(gA.z), ah1[bb]));

            rA = rB; rB = rC; gA = gB;
        }

        // flush every 2 din: keep fp16 chains short (<= 4 fma roundings)
        if (st == 1) {
#pragma unroll
            for (int bb = 0; bb < 32; ++bb) {
                float2 f0 = __half22float2(ah0[bb]);
                float2 f1 = __half22float2(ah1[bb]);
                atomicAdd(O + bb * D_OUT + l,      f0.x + f0.y);
                atomicAdd(O + bb * D_OUT + l + 32, f1.x + f1.y);
                ah0[bb] = hzero;
                ah1[bb] = hzero;
            }
        }
        __syncthreads();   // all reads of tile[st] done before refill at d+2
    }
}

// ---------------------------------------------------------------------------
extern "C" void kernel_launch(void* const* d_in, const int* in_sizes, int n_in,
                              void* d_out, int out_size) {
    const float* x    = (const float*)d_in[0];
    const float* y    = (const float*)d_in[1];
    const float* bias = (const float*)d_in[2];
    float* out = (float*)d_out;

    cudaFuncSetAttribute(kan_main_kernel,
                         cudaFuncAttributeMaxDynamicSharedMemorySize, SMEM_BYTES);

    pchip_pack_kernel<<<D_IN * 4 * 4, 128>>>(y);
    init_out_kernel<<<(BATCH * D_OUT / 4) / 256, 256>>>(bias, out);
    kan_main_kernel<<<dim3(4, 2, NCHUNK), 256, SMEM_BYTES>>>(x, out);
}

// round 14
// speedup vs baseline: 1.2551x; 1.2551x over previous
#include <cuda_runtime.h>
#include <cuda_fp16.h>
#include <cstdint>

// Problem constants
#define D_IN   256
#define D_OUT  256
#define BATCH  512
#define KNOTS  64
#define INV_H  15.75f          // 63/4, exact in fp32
#define H_VAL  (4.0f/63.0f)

#define NCHUNK 32              // din chunks
#define DCHUNK 8               // din per chunk
#define TB     256             // batch rows per block

// B tile: 64 knots x 32 pairs of uint4 {y2(p), hm2(p), y2(p+32), hm2(p+32)} = 32KB
#define TILE_U4   (64*32)      // 2048 uint4
#define TILE_BYTES (TILE_U4*16)

// B smem bytes: 2 tiles (64KB) + cw (32KB) + mbarriers
#define OFF_CW    (2*TILE_BYTES)
#define OFF_MBAR  (OFF_CW + 2048*16)
#define SMEM_BYTES (OFF_MBAR + 64)

// Scratch (device globals; no allocation)
__device__ uint4 g_pack2[(size_t)D_IN * 4 * TILE_U4];           // 33.5 MB

// ---------------------------------------------------------------------------
// PCHIP helpers in RAW-DELTA units (p>0 implies den!=0; underflow -> 0 branch)
// ---------------------------------------------------------------------------
__device__ __forceinline__ float pchip_interior_raw(float D0, float D1) {
    float p   = D0 * D1;
    float m   = __fdividef(2.0f * p, D0 + D1);  // = H * harmonic-mean slope
    return (p > 0.0f) ? m : 0.0f;
}
__device__ __forceinline__ float pchip_endpoint_raw(float Dn, float Df) {
    float m = 1.5f * Dn - 0.5f * Df;            // = H * endpoint slope
    m = (m * Dn <= 0.0f) ? 0.0f : m;
    bool clamp3 = (Dn * Df < 0.0f) && (fabsf(m) > 3.0f * fabsf(Dn));
    return clamp3 ? 3.0f * Dn : m;
}

// 4 records (knots jb..jb+3) for one spline; two aligned LDS.128 window loads.
__device__ __forceinline__ void spline4v(const float* __restrict__ rowbase, int jb,
                                         unsigned y2[4], unsigned h2[4]) {
    float4 a = *(const float4*)(rowbase + jb);       // ly[0..3]
    float4 b = *(const float4*)(rowbase + jb + 4);   // ly[4..7]
    float ly[7] = {a.x, a.y, a.z, a.w, b.x, b.y, b.z};

    float D[6];
#pragma unroll
    for (int k = 0; k < 6; ++k) D[k] = ly[k + 1] - ly[k];

    float s[5];
#pragma unroll
    for (int k = 0; k < 5; ++k) s[k] = pchip_interior_raw(D[k], D[k + 1]);
    if (jb == 0)  s[0] = pchip_endpoint_raw(D[1], D[2]);    // hm0
    if (jb == 60) s[3] = pchip_endpoint_raw(D[3], D[2]);    // hm63

#pragma unroll
    for (int kk = 0; kk < 4; ++kk) {
        __half2 yv = __floats2half2_rn(ly[kk + 1], ly[kk + 2]);
        __half2 hv = __floats2half2_rn(s[kk], s[kk + 1]);
        y2[kk] = *reinterpret_cast<unsigned*>(&yv);
        h2[kk] = *reinterpret_cast<unsigned*>(&hv);
    }
}

// ---------------------------------------------------------------------------
// Kernel A: PCHIP + pack. 4096 blocks x 128 threads.
// ---------------------------------------------------------------------------
__global__ void __launch_bounds__(128) pchip_pack_kernel(const float* __restrict__ y) {
    __shared__ float sy[16 * 68 + 4];              // pitch 68, data at slot +1

    const int t  = threadIdx.x;
    const int bx = blockIdx.x >> 2;                // din*4 + dxt
    const int qt = blockIdx.x & 3;                 // pair quarter

    const float* src = y + (size_t)bx * 4096;
#pragma unroll
    for (int f = t; f < 256; f += 128) {           // stage 4KB
        int r    = f >> 4;
        int col  = (f & 15) << 2;
        int spl  = qt * 8 + ((r < 8) ? r : (r + 24));
        float4 v = *(const float4*)(src + spl * KNOTS + col);
        float* dp = sy + r * 68 + 1 + col;
        dp[0] = v.x; dp[1] = v.y; dp[2] = v.z; dp[3] = v.w;
    }
    __syncthreads();

    const int i  = t & 7;
    const int q  = t >> 3;                         // chunk 0..15
    const int jb = q << 2;                         // 0..60

    unsigned ya[4], hA[4], yb[4], hB[4];
    spline4v(sy + i * 68,       jb, ya, hA);       // spline qt*8+i
    spline4v(sy + (i + 8) * 68, jb, yb, hB);       // spline qt*8+i+32

    uint4* dst = g_pack2 + (size_t)bx * TILE_U4 + jb * 32 + (qt * 8 + i);
#pragma unroll
    for (int kk = 0; kk < 4; ++kk) {
        uint4 rec;
        rec.x = ya[kk]; rec.y = hA[kk]; rec.z = yb[kk]; rec.w = hB[kk];
        dst[kk * 32] = rec;
    }
}

// ---------------------------------------------------------------------------
// Kernel I: out = bias
// ---------------------------------------------------------------------------
__global__ void __launch_bounds__(256) init_out_kernel(
        const float* __restrict__ bias, float* __restrict__ out) {
    int i = blockIdx.x * 256 + threadIdx.x;
    ((float4*)out)[i] = ((const float4*)bias)[i & 63];
}

// ---------------------------------------------------------------------------
// mbarrier / bulk-copy helpers
// ---------------------------------------------------------------------------
__device__ __forceinline__ __half2 u2h(unsigned u) {
    return *reinterpret_cast<__half2*>(&u);
}
__device__ __forceinline__ void mbar_init(unsigned mbar, unsigned count) {
    asm volatile("mbarrier.init.shared.b64 [%0], %1;" :: "r"(mbar), "r"(count) : "memory");
}
__device__ __forceinline__ void mbar_expect_tx(unsigned mbar, unsigned tx) {
    asm volatile("mbarrier.arrive.expect_tx.shared.b64 _, [%0], %1;"
                 :: "r"(mbar), "r"(tx) : "memory");
}
__device__ __forceinline__ void bulk_copy(unsigned dst, const void* src, unsigned bytes,
                                          unsigned mbar) {
    asm volatile("cp.async.bulk.shared::cta.global.mbarrier::complete_tx::bytes "
                 "[%0], [%1], %2, [%3];"
                 :: "r"(dst), "l"(src), "r"(bytes), "r"(mbar) : "memory");
}
__device__ __forceinline__ void mbar_wait(unsigned mbar, unsigned parity) {
    unsigned done;
    asm volatile("{\n\t.reg .pred p;\n\t"
                 "mbarrier.try_wait.parity.acquire.cta.shared::cta.b64 p, [%1], %2;\n\t"
                 "selp.b32 %0, 1, 0, p;\n\t}"
                 : "=r"(done) : "r"(mbar), "r"(parity) : "memory");
    if (!done) {
        asm volatile("{\n\t.reg .pred P1;\n\t"
                     "WAIT_LOOP_%=:\n\t"
                     "mbarrier.try_wait.parity.acquire.cta.shared::cta.b64 P1, [%0], %1, 0x989680;\n\t"
                     "@P1 bra.uni WAIT_DONE_%=;\n\t"
                     "bra.uni WAIT_LOOP_%=;\n\t"
                     "WAIT_DONE_%=:\n\t}"
                     :: "r"(mbar), "r"(parity) : "memory");
    }
}

// ---------------------------------------------------------------------------
// Kernel B: main gather-accumulate.
// Grid (4 dxt, 2 by, 32 ch) = 256 blocks, 256 threads, 2 blocks/SM.
// Inner iter: broadcast LDS.128 + gather LDS.128 + 4 HFMA2 (fused half2
// accumulator chains across all 8 din); single atomic flush at the end.
// ---------------------------------------------------------------------------
__global__ void __launch_bounds__(256, 2) kan_main_kernel(
        const float* __restrict__ x, float* __restrict__ out) {
    extern __shared__ char smem[];
    uint4*   tile  = (uint4*)smem;                    // 2 x TILE_U4
    uint4*   cw    = (uint4*)(smem + OFF_CW);         // 2048: {wy, wh, byteoff, 0}
    unsigned smem_base;
    asm("{ .reg .u64 t; cvta.to.shared.u64 t, %1; cvt.u32.u64 %0, t; }"
        : "=r"(smem_base) : "l"(smem));
    const unsigned mbar0 = smem_base + OFF_MBAR;
    const unsigned mbar1 = smem_base + OFF_MBAR + 8;

    const int dx  = blockIdx.x;   // dout tile of 64 (0..3)
    const int by  = blockIdx.y;   // b tile (0..1)
    const int ch  = blockIdx.z;   // din chunk (0..31)
    const int tid = threadIdx.x;

    if (tid == 0) {
        mbar_init(mbar0, 1);
        mbar_init(mbar1, 1);
    }

    // ---- hermite weights + gather byte offset ----
    for (int i = tid; i < TB * DCHUNK; i += 256) {
        int bb = i >> 3, dl = i & 7;
        float xv = x[(by * TB + bb) * D_IN + ch * DCHUNK + dl];
        xv = fminf(fmaxf(xv, -2.0f), 2.0f);
        float tt = (xv + 2.0f) * INV_H;
        int idx = (int)floorf(tt);
        if (idx > KNOTS - 2) idx = KNOTS - 2;
        if (idx < 0) idx = 0;
        float u  = tt - (float)idx;
        float u2 = u * u, u3 = u2 * u;
        float h00 = 2.0f * u3 - 3.0f * u2 + 1.0f;
        float h10 = u3 - 2.0f * u2 + u;
        float h01 = 3.0f * u2 - 2.0f * u3;
        float h11 = u3 - u2;
        __half2 wy = __floats2half2_rn(h00, h01);
        __half2 wh = __floats2half2_rn(h10, h11);
        uint4 r;
        r.x = *reinterpret_cast<unsigned*>(&wy);
        r.y = *reinterpret_cast<unsigned*>(&wh);
        r.z = (unsigned)(idx << 9);          // idx * 512B (row = 32 uint4)
        r.w = 0;
        cw[i] = r;
    }
    __syncthreads();

    const int w = tid >> 5, l = tid & 31;
    __half2 ah0[32], ah1[32];
    const __half2 hzero = u2h(0u);
#pragma unroll
    for (int bb = 0; bb < 32; ++bb) { ah0[bb] = hzero; ah1[bb] = hzero; }

    const uint4* gsrc = g_pack2 + ((size_t)ch * DCHUNK * 4 + dx) * TILE_U4;

    auto issue_copy = [&](int d, int st) {
        if (tid == 0) {
            unsigned mb = st ? mbar1 : mbar0;
            mbar_expect_tx(mb, TILE_BYTES);
            bulk_copy(smem_base + st * TILE_BYTES, gsrc + (size_t)d * 4 * TILE_U4,
                      TILE_BYTES, mb);
        }
    };

    issue_copy(0, 0);

    int phase0 = 0, phase1 = 0;

    for (int d = 0; d < DCHUNK; ++d) {
        const int st = d & 1;
        if (d < DCHUNK - 1) issue_copy(d + 1, st ^ 1);

        if (st == 0) { mbar_wait(mbar0, phase0); phase0 ^= 1; }
        else         { mbar_wait(mbar1, phase1); phase1 ^= 1; }

        const char* tb = (const char*)(tile + st * TILE_U4) + (l << 4);
        const int base = (w * 32) * DCHUNK + d;

        // software pipeline: records 2 ahead, gathers 1 ahead
        uint4 rA = cw[base];
        uint4 rB = cw[base + DCHUNK];
        uint4 gA = *(const uint4*)(tb + rA.z);
#pragma unroll
        for (int bb = 0; bb < 32; ++bb) {
            uint4 rC, gB;
            if (bb < 30) rC = cw[base + (bb + 2) * DCHUNK];
            if (bb < 31) gB = *(const uint4*)(tb + rB.z);

            ah0[bb] = __hfma2(u2h(rA.y), u2h(gA.y),
                       __hfma2(u2h(rA.x), u2h(gA.x), ah0[bb]));
            ah1[bb] = __hfma2(u2h(rA.y), u2h(gA.w),
                       __hfma2(u2h(rA.x), u2h(gA.z), ah1[bb]));

            rA = rB; rB = rC; gA = gB;
        }
        __syncthreads();   // all reads of tile[st] done before refill at d+2
    }

    // ---- single atomic flush (same atomic volume as the proven R10) ----
    float* O = out + ((size_t)by * TB + w * 32) * D_OUT + dx * 64;
#pragma unroll
    for (int bb = 0; bb < 32; ++bb) {
        float2 f0 = __half22float2(ah0[bb]);
        float2 f1 = __half22float2(ah1[bb]);
        atomicAdd(O + bb * D_OUT + l,      f0.x + f0.y);
        atomicAdd(O + bb * D_OUT + l + 32, f1.x + f1.y);
    }
}

// ---------------------------------------------------------------------------
extern "C" void kernel_launch(void* const* d_in, const int* in_sizes, int n_in,
                              void* d_out, int out_size) {
    const float* x    = (const float*)d_in[0];
    const float* y    = (const float*)d_in[1];
    const float* bias = (const float*)d_in[2];
    float* out = (float*)d_out;

    cudaFuncSetAttribute(kan_main_kernel,
                         cudaFuncAttributeMaxDynamicSharedMemorySize, SMEM_BYTES);

    pchip_pack_kernel<<<D_IN * 4 * 4, 128>>>(y);
    init_out_kernel<<<(BATCH * D_OUT / 4) / 256, 256>>>(bias, out);
    kan_main_kernel<<<dim3(4, 2, NCHUNK), 256, SMEM_BYTES>>>(x, out);
}

// round 15
// speedup vs baseline: 1.3361x; 1.0645x over previous
#include <cuda_runtime.h>
#include <cuda_fp16.h>
#include <cstdint>

// Problem constants
#define D_IN   256
#define D_OUT  256
#define BATCH  512
#define KNOTS  64
#define INV_H  15.75f          // 63/4, exact in fp32
#define H_VAL  (4.0f/63.0f)

#define NCHUNK 32              // din chunks
#define DCHUNK 8               // din per chunk
#define TB     256             // batch rows per block

// B tile: 64 knots x 32 pairs of uint4 {y2(p), hm2(p), y2(p+32), hm2(p+32)} = 32KB
#define TILE_U4   (64*32)      // 2048 uint4
#define TILE_BYTES (TILE_U4*16)

// B smem bytes: 2 tiles (64KB) + cw (32KB) + mbarriers
#define OFF_CW    (2*TILE_BYTES)
#define OFF_MBAR  (OFF_CW + 2048*16)
#define SMEM_BYTES (OFF_MBAR + 64)

// Scratch (device globals; no allocation)
__device__ uint4 g_pack2[(size_t)D_IN * 4 * TILE_U4];           // 33.5 MB

// ---------------------------------------------------------------------------
// PCHIP helpers in RAW-DELTA units (p>0 implies den!=0; underflow -> 0 branch)
// ---------------------------------------------------------------------------
__device__ __forceinline__ float pchip_interior_raw(float D0, float D1) {
    float p   = D0 * D1;
    float m   = __fdividef(2.0f * p, D0 + D1);  // = H * harmonic-mean slope
    return (p > 0.0f) ? m : 0.0f;
}
__device__ __forceinline__ float pchip_endpoint_raw(float Dn, float Df) {
    float m = 1.5f * Dn - 0.5f * Df;            // = H * endpoint slope
    m = (m * Dn <= 0.0f) ? 0.0f : m;
    bool clamp3 = (Dn * Df < 0.0f) && (fabsf(m) > 3.0f * fabsf(Dn));
    return clamp3 ? 3.0f * Dn : m;
}

// 4 records (knots jb..jb+3) for one spline; two aligned LDS.128 window loads.
__device__ __forceinline__ void spline4v(const float* __restrict__ rowbase, int jb,
                                         unsigned y2[4], unsigned h2[4]) {
    float4 a = *(const float4*)(rowbase + jb);       // ly[0..3]
    float4 b = *(const float4*)(rowbase + jb + 4);   // ly[4..7]
    float ly[7] = {a.x, a.y, a.z, a.w, b.x, b.y, b.z};

    float D[6];
#pragma unroll
    for (int k = 0; k < 6; ++k) D[k] = ly[k + 1] - ly[k];

    float s[5];
#pragma unroll
    for (int k = 0; k < 5; ++k) s[k] = pchip_interior_raw(D[k], D[k + 1]);
    if (jb == 0)  s[0] = pchip_endpoint_raw(D[1], D[2]);    // hm0
    if (jb == 60) s[3] = pchip_endpoint_raw(D[3], D[2]);    // hm63

#pragma unroll
    for (int kk = 0; kk < 4; ++kk) {
        __half2 yv = __floats2half2_rn(ly[kk + 1], ly[kk + 2]);
        __half2 hv = __floats2half2_rn(s[kk], s[kk + 1]);
        y2[kk] = *reinterpret_cast<unsigned*>(&yv);
        h2[kk] = *reinterpret_cast<unsigned*>(&hv);
    }
}

// ---------------------------------------------------------------------------
// Kernel A: PCHIP + pack. 4096 blocks x 128 threads.
// ---------------------------------------------------------------------------
__global__ void __launch_bounds__(128) pchip_pack_kernel(const float* __restrict__ y) {
    __shared__ float sy[16 * 68 + 4];              // pitch 68, data at slot +1

    const int t  = threadIdx.x;
    const int bx = blockIdx.x >> 2;                // din*4 + dxt
    const int qt = blockIdx.x & 3;                 // pair quarter

    const float* src = y + (size_t)bx * 4096;
#pragma unroll
    for (int f = t; f < 256; f += 128) {           // stage 4KB
        int r    = f >> 4;
        int col  = (f & 15) << 2;
        int spl  = qt * 8 + ((r < 8) ? r : (r + 24));
        float4 v = *(const float4*)(src + spl * KNOTS + col);
        float* dp = sy + r * 68 + 1 + col;
        dp[0] = v.x; dp[1] = v.y; dp[2] = v.z; dp[3] = v.w;
    }
    __syncthreads();

    const int i  = t & 7;
    const int q  = t >> 3;                         // chunk 0..15
    const int jb = q << 2;                         // 0..60

    unsigned ya[4], hA[4], yb[4], hB[4];
    spline4v(sy + i * 68,       jb, ya, hA);       // spline qt*8+i
    spline4v(sy + (i + 8) * 68, jb, yb, hB);       // spline qt*8+i+32

    uint4* dst = g_pack2 + (size_t)bx * TILE_U4 + jb * 32 + (qt * 8 + i);
#pragma unroll
    for (int kk = 0; kk < 4; ++kk) {
        uint4 rec;
        rec.x = ya[kk]; rec.y = hA[kk]; rec.z = yb[kk]; rec.w = hB[kk];
        dst[kk * 32] = rec;
    }
}

// ---------------------------------------------------------------------------
// Kernel I: out = bias
// ---------------------------------------------------------------------------
__global__ void __launch_bounds__(256) init_out_kernel(
        const float* __restrict__ bias, float* __restrict__ out) {
    int i = blockIdx.x * 256 + threadIdx.x;
    ((float4*)out)[i] = ((const float4*)bias)[i & 63];
}

// ---------------------------------------------------------------------------
// mbarrier / bulk-copy helpers
// ---------------------------------------------------------------------------
__device__ __forceinline__ __half2 u2h(unsigned u) {
    return *reinterpret_cast<__half2*>(&u);
}
__device__ __forceinline__ void mbar_init(unsigned mbar, unsigned count) {
    asm volatile("mbarrier.init.shared.b64 [%0], %1;" :: "r"(mbar), "r"(count) : "memory");
}
__device__ __forceinline__ void mbar_expect_tx(unsigned mbar, unsigned tx) {
    asm volatile("mbarrier.arrive.expect_tx.shared.b64 _, [%0], %1;"
                 :: "r"(mbar), "r"(tx) : "memory");
}
__device__ __forceinline__ void bulk_copy(unsigned dst, const void* src, unsigned bytes,
                                          unsigned mbar) {
    asm volatile("cp.async.bulk.shared::cta.global.mbarrier::complete_tx::bytes "
                 "[%0], [%1], %2, [%3];"
                 :: "r"(dst), "l"(src), "r"(bytes), "r"(mbar) : "memory");
}
__device__ __forceinline__ void mbar_wait(unsigned mbar, unsigned parity) {
    unsigned done;
    asm volatile("{\n\t.reg .pred p;\n\t"
                 "mbarrier.try_wait.parity.acquire.cta.shared::cta.b64 p, [%1], %2;\n\t"
                 "selp.b32 %0, 1, 0, p;\n\t}"
                 : "=r"(done) : "r"(mbar), "r"(parity) : "memory");
    if (!done) {
        asm volatile("{\n\t.reg .pred P1;\n\t"
                     "WAIT_LOOP_%=:\n\t"
                     "mbarrier.try_wait.parity.acquire.cta.shared::cta.b64 P1, [%0], %1, 0x989680;\n\t"
                     "@P1 bra.uni WAIT_DONE_%=;\n\t"
                     "bra.uni WAIT_LOOP_%=;\n\t"
                     "WAIT_DONE_%=:\n\t}"
                     :: "r"(mbar), "r"(parity) : "memory");
    }
}

// ---------------------------------------------------------------------------
// Kernel B: main gather-accumulate (R10 core; TMA fills hoisted ahead of
// weight prep so the first two tile loads overlap the prep phase).
// Grid (4 dxt, 2 by, 32 ch) = 256 blocks, 256 threads, 2 blocks/SM.
// ---------------------------------------------------------------------------
__global__ void __launch_bounds__(256, 2) kan_main_kernel(
        const float* __restrict__ x, float* __restrict__ out) {
    extern __shared__ char smem[];
    uint4*   tile  = (uint4*)smem;                    // 2 x TILE_U4
    uint4*   cw    = (uint4*)(smem + OFF_CW);         // 2048: {wy, wh, byteoff, 0}
    unsigned smem_base;
    asm("{ .reg .u64 t; cvta.to.shared.u64 t, %1; cvt.u32.u64 %0, t; }"
        : "=r"(smem_base) : "l"(smem));
    const unsigned mbar0 = smem_base + OFF_MBAR;
    const unsigned mbar1 = smem_base + OFF_MBAR + 8;

    const int dx  = blockIdx.x;   // dout tile of 64 (0..3)
    const int by  = blockIdx.y;   // b tile (0..1)
    const int ch  = blockIdx.z;   // din chunk (0..31)
    const int tid = threadIdx.x;

    const uint4* gsrc = g_pack2 + ((size_t)ch * DCHUNK * 4 + dx) * TILE_U4;

    // ---- init barriers and start BOTH tile fills before weight prep ----
    if (tid == 0) {
        mbar_init(mbar0, 1);
        mbar_init(mbar1, 1);
        asm volatile("fence.proxy.async.shared::cta;" ::: "memory");
        mbar_expect_tx(mbar0, TILE_BYTES);
        bulk_copy(smem_base, gsrc, TILE_BYTES, mbar0);
        mbar_expect_tx(mbar1, TILE_BYTES);
        bulk_copy(smem_base + TILE_BYTES, gsrc + 4 * TILE_U4, TILE_BYTES, mbar1);
    }

    // ---- hermite weights + gather byte offset (overlaps the TMA fills) ----
    for (int i = tid; i < TB * DCHUNK; i += 256) {
        int bb = i >> 3, dl = i & 7;
        float xv = x[(by * TB + bb) * D_IN + ch * DCHUNK + dl];
        xv = fminf(fmaxf(xv, -2.0f), 2.0f);
        float tt = (xv + 2.0f) * INV_H;
        int idx = (int)floorf(tt);
        if (idx > KNOTS - 2) idx = KNOTS - 2;
        if (idx < 0) idx = 0;
        float u  = tt - (float)idx;
        float u2 = u * u, u3 = u2 * u;
        float h00 = 2.0f * u3 - 3.0f * u2 + 1.0f;
        float h10 = u3 - 2.0f * u2 + u;
        float h01 = 3.0f * u2 - 2.0f * u3;
        float h11 = u3 - u2;
        __half2 wy = __floats2half2_rn(h00, h01);
        __half2 wh = __floats2half2_rn(h10, h11);
        uint4 r;
        r.x = *reinterpret_cast<unsigned*>(&wy);
        r.y = *reinterpret_cast<unsigned*>(&wh);
        r.z = (unsigned)(idx << 9);          // idx * 512B (row = 32 uint4)
        r.w = 0;
        cw[i] = r;
    }
    __syncthreads();                         // cw ready; mbar inits visible

    const int w = tid >> 5, l = tid & 31;
    float acc0[32], acc1[32];
#pragma unroll
    for (int bb = 0; bb < 32; ++bb) { acc0[bb] = 0.0f; acc1[bb] = 0.0f; }

    int phase0 = 0, phase1 = 0;

    for (int d = 0; d < DCHUNK; ++d) {
        const int st = d & 1;

        if (st == 0) { mbar_wait(mbar0, phase0); phase0 ^= 1; }
        else         { mbar_wait(mbar1, phase1); phase1 ^= 1; }

        const char* tb = (const char*)(tile + st * TILE_U4) + (l << 4);
        const int base = (w * 32) * DCHUNK + d;

        // software pipeline: records 2 ahead, gathers 1 ahead
        uint4 rA = cw[base];
        uint4 rB = cw[base + DCHUNK];
        uint4 gA = *(const uint4*)(tb + rA.z);
#pragma unroll
        for (int bb = 0; bb < 32; ++bb) {
            uint4 rC, gB;
            if (bb < 30) rC = cw[base + (bb + 2) * DCHUNK];
            if (bb < 31) gB = *(const uint4*)(tb + rB.z);

            __half2 p0 = __hfma2(u2h(rA.y), u2h(gA.y), __hmul2(u2h(rA.x), u2h(gA.x)));
            __half2 p1 = __hfma2(u2h(rA.y), u2h(gA.w), __hmul2(u2h(rA.x), u2h(gA.z)));
            acc0[bb] += __half2float(__hadd(__low2half(p0), __high2half(p0)));
            acc1[bb] += __half2float(__hadd(__low2half(p1), __high2half(p1)));

            rA = rB; rB = rC; gA = gB;
        }
        __syncthreads();   // all reads of tile[st] complete

        // refill this buffer for stage d+2 (now provably safe)
        if (d + 2 < DCHUNK && tid == 0) {
            unsigned mb = st ? mbar1 : mbar0;
            mbar_expect_tx(mb, TILE_BYTES);
            bulk_copy(smem_base + st * TILE_BYTES,
                      gsrc + (size_t)(d + 2) * 4 * TILE_U4, TILE_BYTES, mb);
        }
    }

    // ---- atomic accumulate into out (coalesced per warp) ----
    float* O = out + ((size_t)by * TB + w * 32) * D_OUT + dx * 64;
#pragma unroll
    for (int bb = 0; bb < 32; ++bb) {
        atomicAdd(O + bb * D_OUT + l,      acc0[bb]);
        atomicAdd(O + bb * D_OUT + l + 32, acc1[bb]);
    }
}

// ---------------------------------------------------------------------------
extern "C" void kernel_launch(void* const* d_in, const int* in_sizes, int n_in,
                              void* d_out, int out_size) {
    const float* x    = (const float*)d_in[0];
    const float* y    = (const float*)d_in[1];
    const float* bias = (const float*)d_in[2];
    float* out = (float*)d_out;

    cudaFuncSetAttribute(kan_main_kernel,
                         cudaFuncAttributeMaxDynamicSharedMemorySize, SMEM_BYTES);

    pchip_pack_kernel<<<D_IN * 4 * 4, 128>>>(y);
    init_out_kernel<<<(BATCH * D_OUT / 4) / 256, 256>>>(bias, out);
    kan_main_kernel<<<dim3(4, 2, NCHUNK), 256, SMEM_BYTES>>>(x, out);
}